// round 8
// baseline (speedup 1.0000x reference)
#include <cuda_runtime.h>

// SpikeLoss: loss = 0.5 * sum( (outputs - psp(target))^2 ), tau = 5
// Persistent warp-per-2-rows kernel with REGISTER PREFETCH pipeline and an
// eager local transform: per lane-segment (4 steps) compute prefix syns
// s1..s4, fold into u_t = o_t - s_t/tau, keep b = s4. After the uniform-
// multiplier Kogge-Stone scan gives the carry c, d_t = u_t - (D^t/tau)*c.
// Deterministic fused reduction via last-block ticket.

#define T_STEPS   100
#define ROW_V     (T_STEPS / 4)   // 25 float4 per row
#define BLOCK     512
#define WPB       (BLOCK / 32)    // 16 warps -> 32 rows per iteration
#define GRID      592
#define STRIDE    (GRID * WPB)
#define MAX_BLOCKS 1024

__device__ float        g_partials[MAX_BLOCKS];
__device__ unsigned int g_count = 0;

__global__ void __launch_bounds__(BLOCK, 2)
spike_loss_pipe(const float* __restrict__ outputs,
                const float* __restrict__ target,
                float* __restrict__ out,
                int rows)
{
    const int tid  = threadIdx.x;
    const int lane = tid & 31;
    const int wid  = tid >> 5;

    const float D  = 0.8f;      // decay
    const float IT = 0.2f;      // 1/tau
    // K_t = IT * D^t
    const float K1 = 0.16f, K2 = 0.128f, K3 = 0.1024f, K4 = 0.08192f;
    // Kogge-Stone uniform multipliers (0.8^4)^(2^r)
    const float C0 = 0.4096f;
    const float C1 = 0.16777216f;
    const float C2 = 2.8147497671e-2f;
    const float C3 = 7.9228162514e-4f;
    const float C4 = 6.2771017354e-7f;

    const bool lv = (lane < ROW_V);
    const float4* __restrict__ x4 = reinterpret_cast<const float4*>(target);
    const float4* __restrict__ o4 = reinterpret_cast<const float4*>(outputs);

    const int npairs = rows >> 1;
    float acc = 0.0f;

    int pair   = blockIdx.x * WPB + wid;
    bool valid = pair < npairs;

    float4 xa = make_float4(0.f,0.f,0.f,0.f), xb = xa, oa = xa, ob = xa;
    if (valid && lv) {
        const size_t ra = (size_t)(2 * pair) * ROW_V + lane;
        xa = __ldg(&x4[ra]);  xb = __ldg(&x4[ra + ROW_V]);
        oa = __ldg(&o4[ra]);  ob = __ldg(&o4[ra + ROW_V]);
    }

    while (valid) {
        // ---- prefetch next iteration ----
        const int  npair  = pair + STRIDE;
        const bool nvalid = npair < npairs;
        float4 nxa = make_float4(0.f,0.f,0.f,0.f), nxb = nxa, noa = nxa, nob = nxa;
        if (nvalid && lv) {
            const size_t ra = (size_t)(2 * npair) * ROW_V + lane;
            nxa = __ldg(&x4[ra]);  nxb = __ldg(&x4[ra + ROW_V]);
            noa = __ldg(&o4[ra]);  nob = __ldg(&o4[ra + ROW_V]);
        }

        // ---- eager local transform (frees x/o registers) ----
        float s1A = xa.x;
        float s2A = fmaf(D, s1A, xa.y);
        float s3A = fmaf(D, s2A, xa.z);
        float bA  = fmaf(D, s3A, xa.w);
        float u1A = fmaf(-IT, s1A, oa.x);
        float u2A = fmaf(-IT, s2A, oa.y);
        float u3A = fmaf(-IT, s3A, oa.z);
        float u4A = fmaf(-IT, bA,  oa.w);

        float s1B = xb.x;
        float s2B = fmaf(D, s1B, xb.y);
        float s3B = fmaf(D, s2B, xb.z);
        float bB  = fmaf(D, s3B, xb.w);
        float u1B = fmaf(-IT, s1B, ob.x);
        float u2B = fmaf(-IT, s2B, ob.y);
        float u3B = fmaf(-IT, s3B, ob.z);
        float u4B = fmaf(-IT, bB,  ob.w);

        // ---- Kogge-Stone scan, two chains interleaved ----
        float pA, pB;
        pA = __shfl_up_sync(0xFFFFFFFFu, bA, 1);
        pB = __shfl_up_sync(0xFFFFFFFFu, bB, 1);
        if (lane >= 1)  { bA = fmaf(C0, pA, bA); bB = fmaf(C0, pB, bB); }
        pA = __shfl_up_sync(0xFFFFFFFFu, bA, 2);
        pB = __shfl_up_sync(0xFFFFFFFFu, bB, 2);
        if (lane >= 2)  { bA = fmaf(C1, pA, bA); bB = fmaf(C1, pB, bB); }
        pA = __shfl_up_sync(0xFFFFFFFFu, bA, 4);
        pB = __shfl_up_sync(0xFFFFFFFFu, bB, 4);
        if (lane >= 4)  { bA = fmaf(C2, pA, bA); bB = fmaf(C2, pB, bB); }
        pA = __shfl_up_sync(0xFFFFFFFFu, bA, 8);
        pB = __shfl_up_sync(0xFFFFFFFFu, bB, 8);
        if (lane >= 8)  { bA = fmaf(C3, pA, bA); bB = fmaf(C3, pB, bB); }
        pA = __shfl_up_sync(0xFFFFFFFFu, bA, 16);
        pB = __shfl_up_sync(0xFFFFFFFFu, bB, 16);
        if (lane >= 16) { bA = fmaf(C4, pA, bA); bB = fmaf(C4, pB, bB); }

        // exclusive carry
        float cA = __shfl_up_sync(0xFFFFFFFFu, bA, 1);
        float cB = __shfl_up_sync(0xFFFFFFFFu, bB, 1);
        if (lane == 0) { cA = 0.0f; cB = 0.0f; }

        // ---- independent finals ----
        if (lv) {
            float d;
            d = fmaf(-K1, cA, u1A); acc = fmaf(d, d, acc);
            d = fmaf(-K2, cA, u2A); acc = fmaf(d, d, acc);
            d = fmaf(-K3, cA, u3A); acc = fmaf(d, d, acc);
            d = fmaf(-K4, cA, u4A); acc = fmaf(d, d, acc);
            d = fmaf(-K1, cB, u1B); acc = fmaf(d, d, acc);
            d = fmaf(-K2, cB, u2B); acc = fmaf(d, d, acc);
            d = fmaf(-K3, cB, u3B); acc = fmaf(d, d, acc);
            d = fmaf(-K4, cB, u4B); acc = fmaf(d, d, acc);
        }

        // rotate buffers
        xa = nxa; xb = nxb; oa = noa; ob = nob;
        pair = npair; valid = nvalid;
    }

    // ---- once-per-block deterministic reduction ----
    __shared__ float warp_sums[WPB];
    __shared__ int   is_last;

    #pragma unroll
    for (int off = 16; off > 0; off >>= 1)
        acc += __shfl_down_sync(0xFFFFFFFFu, acc, off);
    if (lane == 0) warp_sums[wid] = acc;
    __syncthreads();

    if (tid == 0) {
        float bsum = 0.0f;
        #pragma unroll
        for (int w = 0; w < WPB; ++w) bsum += warp_sums[w];
        g_partials[blockIdx.x] = bsum;
        __threadfence();
        unsigned int ticket = atomicAdd(&g_count, 1u);
        is_last = (ticket == gridDim.x - 1) ? 1 : 0;
    }
    __syncthreads();

    if (is_last) {
        const int nblocks = gridDim.x;
        float v = 0.0f;
        for (int i = tid; i < nblocks; i += BLOCK)
            v += g_partials[i];

        #pragma unroll
        for (int off = 16; off > 0; off >>= 1)
            v += __shfl_down_sync(0xFFFFFFFFu, v, off);
        if (lane == 0) warp_sums[wid] = v;
        __syncthreads();

        if (tid == 0) {
            float stot = 0.0f;
            #pragma unroll
            for (int w = 0; w < WPB; ++w) stot += warp_sums[w];
            *out = 0.5f * stot;
            g_count = 0;   // reset for graph replay
        }
    }
}

extern "C" void kernel_launch(void* const* d_in, const int* in_sizes, int n_in,
                              void* d_out, int out_size)
{
    const float* outputs = (const float*)d_in[0];
    const float* target  = (const float*)d_in[1];
    float* out = (float*)d_out;

    const int n    = in_sizes[0];
    const int rows = n / T_STEPS;   // 131072

    spike_loss_pipe<<<GRID, BLOCK>>>(outputs, target, out, rows);
}